// round 4
// baseline (speedup 1.0000x reference)
#include <cuda_runtime.h>
#include <math_constants.h>

#define FD 128          // IN_DIM == NUM_HEADS*HEAD_DIM
#define NH 4
#define NN_MAX 50000
#define NE_MAX 800000

// Scratch (device globals: allocation-free per harness rules)
__device__ float g_feat[NN_MAX * FD];   // projected features [N,128]
__device__ float g_el[NN_MAX * NH];     // per-node left attn term
__device__ float g_er[NN_MAX * NH];     // per-node right attn term
__device__ float g_e[NE_MAX * NH];      // per-edge logits

// ---------------------------------------------------------------------------
// Kernel 1: feat = x @ W^T  (warp-per-row, W^T staged in SMEM), fused el/er.
// ---------------------------------------------------------------------------
__global__ void __launch_bounds__(256, 1) gat_gemm(
    const float* __restrict__ x, const float* __restrict__ W,
    const float* __restrict__ al, const float* __restrict__ ar, int n_nodes)
{
    extern __shared__ float smem[];
    float* sWt = smem;              // [128][128]: sWt[k*128+o] = W[o*128+k]
    float* sAl = smem + FD * FD;    // [128]
    float* sAr = sAl + FD;          // [128]

    const int tid = threadIdx.x;
    for (int idx = tid; idx < FD * FD; idx += blockDim.x) {
        int o = idx >> 7, k = idx & 127;
        sWt[k * FD + o] = W[idx];
    }
    if (tid < FD) { sAl[tid] = al[tid]; sAr[tid] = ar[tid]; }
    __syncthreads();

    const int warp = tid >> 5, lane = tid & 31;
    const float4 alv = *(const float4*)(sAl + lane * 4);
    const float4 arv = *(const float4*)(sAr + lane * 4);

    for (int row = blockIdx.x * 8 + warp; row < n_nodes; row += gridDim.x * 8) {
        float4 xv = *(const float4*)(x + row * FD + lane * 4);
        float ax = 0.f, ay = 0.f, az = 0.f, aw = 0.f;
#pragma unroll
        for (int k4 = 0; k4 < 32; ++k4) {
            float b0 = __shfl_sync(0xffffffffu, xv.x, k4);
            float b1 = __shfl_sync(0xffffffffu, xv.y, k4);
            float b2 = __shfl_sync(0xffffffffu, xv.z, k4);
            float b3 = __shfl_sync(0xffffffffu, xv.w, k4);
            float4 w0 = *(const float4*)(sWt + (k4 * 4 + 0) * FD + lane * 4);
            float4 w1 = *(const float4*)(sWt + (k4 * 4 + 1) * FD + lane * 4);
            float4 w2 = *(const float4*)(sWt + (k4 * 4 + 2) * FD + lane * 4);
            float4 w3 = *(const float4*)(sWt + (k4 * 4 + 3) * FD + lane * 4);
            ax = fmaf(b0, w0.x, fmaf(b1, w1.x, fmaf(b2, w2.x, fmaf(b3, w3.x, ax))));
            ay = fmaf(b0, w0.y, fmaf(b1, w1.y, fmaf(b2, w2.y, fmaf(b3, w3.y, ay))));
            az = fmaf(b0, w0.z, fmaf(b1, w1.z, fmaf(b2, w2.z, fmaf(b3, w3.z, az))));
            aw = fmaf(b0, w0.w, fmaf(b1, w1.w, fmaf(b2, w2.w, fmaf(b3, w3.w, aw))));
        }
        *(float4*)(g_feat + row * FD + lane * 4) = make_float4(ax, ay, az, aw);

        // el/er: each lane owns 4 dims of one head (8 lanes per head)
        float pl = ax * alv.x + ay * alv.y + az * alv.z + aw * alv.w;
        float pr = ax * arv.x + ay * arv.y + az * arv.z + aw * arv.w;
#pragma unroll
        for (int off = 4; off; off >>= 1) {
            pl += __shfl_down_sync(0xffffffffu, pl, off);
            pr += __shfl_down_sync(0xffffffffu, pr, off);
        }
        if ((lane & 7) == 0) {
            g_el[row * NH + (lane >> 3)] = pl;
            g_er[row * NH + (lane >> 3)] = pr;
        }
    }
}

// ---------------------------------------------------------------------------
// Kernel 2: per-dst-node edge softmax + weighted aggregation.
// dst is sorted => each node's edges are a contiguous range (binary search).
// One warp per node.
// ---------------------------------------------------------------------------
__global__ void __launch_bounds__(256, 1) gat_agg(
    const int* __restrict__ src, const int* __restrict__ dst,
    float* __restrict__ out, int n_nodes, int n_edges)
{
    const unsigned FULL = 0xffffffffu;
    const int lane = threadIdx.x & 31;
    const int gw = (blockIdx.x * blockDim.x + threadIdx.x) >> 5;
    const int nw = (gridDim.x * blockDim.x) >> 5;

    for (int n = gw; n < n_nodes; n += nw) {
        // segment [s,e): lower/upper bound of n in sorted dst (uniform per warp)
        int lo = 0, hi = n_edges;
        while (lo < hi) { int mid = (lo + hi) >> 1; if (dst[mid] < n) lo = mid + 1; else hi = mid; }
        const int s = lo;
        hi = n_edges;
        while (lo < hi) { int mid = (lo + hi) >> 1; if (dst[mid] <= n) lo = mid + 1; else hi = mid; }
        const int e = lo;

        float ax = 0.f, ay = 0.f, az = 0.f, aw = 0.f;
        if (s < e) {
            const float4 ern = *(const float4*)(g_er + n * NH);

            // pass 1: logits + leaky relu + per-head max
            float mx0 = -CUDART_INF_F, mx1 = -CUDART_INF_F;
            float mx2 = -CUDART_INF_F, mx3 = -CUDART_INF_F;
            for (int i = s + lane; i < e; i += 32) {
                int sv = src[i];
                float4 elv = *(const float4*)(g_el + sv * NH);
                float e0 = elv.x + ern.x; e0 = e0 > 0.f ? e0 : 0.2f * e0;
                float e1 = elv.y + ern.y; e1 = e1 > 0.f ? e1 : 0.2f * e1;
                float e2 = elv.z + ern.z; e2 = e2 > 0.f ? e2 : 0.2f * e2;
                float e3 = elv.w + ern.w; e3 = e3 > 0.f ? e3 : 0.2f * e3;
                *(float4*)(g_e + i * NH) = make_float4(e0, e1, e2, e3);
                mx0 = fmaxf(mx0, e0); mx1 = fmaxf(mx1, e1);
                mx2 = fmaxf(mx2, e2); mx3 = fmaxf(mx3, e3);
            }
#pragma unroll
            for (int off = 16; off; off >>= 1) {
                mx0 = fmaxf(mx0, __shfl_xor_sync(FULL, mx0, off));
                mx1 = fmaxf(mx1, __shfl_xor_sync(FULL, mx1, off));
                mx2 = fmaxf(mx2, __shfl_xor_sync(FULL, mx2, off));
                mx3 = fmaxf(mx3, __shfl_xor_sync(FULL, mx3, off));
            }

            // pass 2: softmax denominators
            float s0 = 0.f, s1 = 0.f, s2 = 0.f, s3 = 0.f;
            for (int i = s + lane; i < e; i += 32) {
                float4 ev = *(const float4*)(g_e + i * NH);
                s0 += __expf(ev.x - mx0); s1 += __expf(ev.y - mx1);
                s2 += __expf(ev.z - mx2); s3 += __expf(ev.w - mx3);
            }
#pragma unroll
            for (int off = 16; off; off >>= 1) {
                s0 += __shfl_xor_sync(FULL, s0, off);
                s1 += __shfl_xor_sync(FULL, s1, off);
                s2 += __shfl_xor_sync(FULL, s2, off);
                s3 += __shfl_xor_sync(FULL, s3, off);
            }

            const int h = lane >> 3;   // lane's head (4 dims of this head)
            const float mh = (h == 0) ? mx0 : (h == 1) ? mx1 : (h == 2) ? mx2 : mx3;
            const float dh = (h == 0) ? s0  : (h == 1) ? s1  : (h == 2) ? s2  : s3;
            const float rdh = 1.0f / dh;

            // pass 3: weighted aggregation; warp walks edges, all lanes load
            // one 512B feat row cooperatively (lane -> float4 of its 4 dims)
            for (int i = s; i < e; ++i) {
                float ge = g_e[i * NH + h];
                float w = __expf(ge - mh) * rdh;
                int sv = src[i];
                float4 f = *(const float4*)(g_feat + sv * FD + lane * 4);
                ax = fmaf(w, f.x, ax); ay = fmaf(w, f.y, ay);
                az = fmaf(w, f.z, az); aw = fmaf(w, f.w, aw);
            }
        }
        *(float4*)(out + n * FD + lane * 4) = make_float4(ax, ay, az, aw);
    }
}

// ---------------------------------------------------------------------------
extern "C" void kernel_launch(void* const* d_in, const int* in_sizes, int n_in,
                              void* d_out, int out_size)
{
    const float* x   = (const float*)d_in[0];   // [N,128]
    const float* W   = (const float*)d_in[1];   // [128,128]
    const float* al  = (const float*)d_in[2];   // [4,32]
    const float* ar  = (const float*)d_in[3];   // [4,32]
    const int*   src = (const int*)d_in[4];     // [E]
    const int*   dst = (const int*)d_in[5];     // [E], sorted
    float* out = (float*)d_out;

    const int n_nodes = in_sizes[0] / FD;
    const int n_edges = in_sizes[4];

    const size_t smem = (size_t)(FD * FD + 2 * FD) * sizeof(float);
    cudaFuncSetAttribute(gat_gemm, cudaFuncAttributeMaxDynamicSharedMemorySize, (int)smem);

    const int gblocks = (n_nodes + 7) / 8;      // 8 warp-rows per block
    gat_gemm<<<gblocks, 256, smem>>>(x, W, al, ar, n_nodes);

    const int ablocks = (n_nodes + 7) / 8;      // 8 warp-nodes per block
    gat_agg<<<ablocks, 256>>>(src, dst, out, n_nodes, n_edges);
}

// round 5
// speedup vs baseline: 6.4410x; 6.4410x over previous
#include <cuda_runtime.h>

#define FD 128
#define NH 4
#define NN_MAX 50000
#define NE_MAX 800000
#define BM 64

// Scratch (device globals: allocation-free per harness rules)
__device__ float g_feat[NN_MAX * FD];     // projected features [N,128]
__device__ float g_el[NN_MAX * NH];
__device__ float g_er[NN_MAX * NH];
__device__ float g_wt[FD * FD];           // W transposed: g_wt[k][o]
__device__ int   g_rowstart[NN_MAX + 1];  // CSR-style dst segment starts

// ---------------------------------------------------------------------------
// f32x2 packed helpers (Blackwell FFMA2: full-rate fp32, 2 FMA/instr)
// ---------------------------------------------------------------------------
__device__ __forceinline__ void ffma2(unsigned long long& d,
                                      unsigned long long a,
                                      unsigned long long b) {
    asm("fma.rn.f32x2 %0, %1, %2, %0;" : "+l"(d) : "l"(a), "l"(b));
}
__device__ __forceinline__ unsigned long long pk2(float a) {
    unsigned long long r;
    asm("mov.b64 %0, {%1, %2};" : "=l"(r) : "f"(a), "f"(a));
    return r;
}
__device__ __forceinline__ float2 upk(unsigned long long v) {
    float2 r;
    asm("mov.b64 {%0, %1}, %2;" : "=f"(r.x), "=f"(r.y) : "l"(v));
    return r;
}

// ---------------------------------------------------------------------------
// Kernel 0a: transpose W (128x128) once so the GEMM stages it conflict-free.
// ---------------------------------------------------------------------------
__global__ void gat_wt(const float* __restrict__ W) {
    __shared__ float t[32][33];
    int bx = blockIdx.x * 32, by = blockIdx.y * 32;
#pragma unroll
    for (int j = 0; j < 32; j += 8)
        t[threadIdx.y + j][threadIdx.x] = W[(by + threadIdx.y + j) * FD + bx + threadIdx.x];
    __syncthreads();
#pragma unroll
    for (int j = 0; j < 32; j += 8)
        g_wt[(bx + threadIdx.y + j) * FD + by + threadIdx.x] = t[threadIdx.x][threadIdx.y + j];
}

// ---------------------------------------------------------------------------
// Kernel 0b: segment starts from sorted dst.
// ---------------------------------------------------------------------------
__global__ void gat_seg(const int* __restrict__ dst, int n_edges, int n_nodes) {
    int i = blockIdx.x * blockDim.x + threadIdx.x;
    if (i < n_edges) {
        int d = dst[i];
        int prev = (i == 0) ? -1 : dst[i - 1];
        for (int n = prev + 1; n <= d; ++n) g_rowstart[n] = i;
        if (i == n_edges - 1)
            for (int n = d + 1; n <= n_nodes; ++n) g_rowstart[n] = n_edges;
    }
}

// ---------------------------------------------------------------------------
// Kernel 1: feat = x @ W^T via register-blocked SGEMM with f32x2 FMAs.
// Tile: BM=64 rows x 128 cols, K=128 fully resident in SMEM.
// 256 threads, each computes 4 rows x 8 cols (cols tx*4 and tx*4+64).
// Fused epilogue: el/er dots + 8-lane shfl reductions.
// ---------------------------------------------------------------------------
__global__ void __launch_bounds__(256) gat_gemm(
    const float* __restrict__ x,
    const float* __restrict__ al, const float* __restrict__ ar, int n_nodes)
{
    extern __shared__ float smem[];
    float* xs  = smem;                 // [64][128] node rows (natural layout)
    float* ws  = smem + BM * FD;       // [128][128] W^T rows (k-major)
    float* als = ws + FD * FD;         // [128]
    float* ars = als + FD;             // [128]

    const int tid = threadIdx.x;
    const int rb = blockIdx.x * BM;

    // Stage W^T (coalesced float4, natural layout -> conflict-free everywhere)
    for (int p = tid; p < FD * FD / 4; p += 256)
        ((float4*)ws)[p] = ((const float4*)g_wt)[p];
    // Stage x tile (clamp OOB rows; their results are discarded)
    for (int p = tid; p < BM * FD / 4; p += 256) {
        int r = p >> 5, k4 = p & 31;
        int gr = rb + r; if (gr >= n_nodes) gr = n_nodes - 1;
        ((float4*)xs)[p] = *(const float4*)(x + gr * FD + k4 * 4);
    }
    if (tid < FD) { als[tid] = al[tid]; ars[tid] = ar[tid]; }
    __syncthreads();

    const int tx = tid & 15, ty = tid >> 4;
    const float* xr = xs + (ty * 4) * FD;

    unsigned long long acc[4][4];
#pragma unroll
    for (int j = 0; j < 4; ++j)
#pragma unroll
        for (int p = 0; p < 4; ++p) acc[j][p] = 0ull;

#pragma unroll 8
    for (int k = 0; k < FD; ++k) {
        // 4 row values: 2-address broadcast LDS (conflict-free)
        unsigned long long r0 = pk2(xr[k]);
        unsigned long long r1 = pk2(xr[FD + k]);
        unsigned long long r2 = pk2(xr[2 * FD + k]);
        unsigned long long r3 = pk2(xr[3 * FD + k]);
        // 8 col values: two LDS.128, lanes stride 16B (conflict-free)
        ulonglong2 cA = *(const ulonglong2*)(ws + k * FD + tx * 4);
        ulonglong2 cB = *(const ulonglong2*)(ws + k * FD + 64 + tx * 4);
        ffma2(acc[0][0], r0, cA.x); ffma2(acc[0][1], r0, cA.y);
        ffma2(acc[0][2], r0, cB.x); ffma2(acc[0][3], r0, cB.y);
        ffma2(acc[1][0], r1, cA.x); ffma2(acc[1][1], r1, cA.y);
        ffma2(acc[1][2], r1, cB.x); ffma2(acc[1][3], r1, cB.y);
        ffma2(acc[2][0], r2, cA.x); ffma2(acc[2][1], r2, cA.y);
        ffma2(acc[2][2], r2, cB.x); ffma2(acc[2][3], r2, cB.y);
        ffma2(acc[3][0], r3, cA.x); ffma2(acc[3][1], r3, cA.y);
        ffma2(acc[3][2], r3, cB.x); ffma2(acc[3][3], r3, cB.y);
    }

    // Epilogue: store feat + fused el/er
    const float4 alA = *(const float4*)(als + tx * 4);
    const float4 alB = *(const float4*)(als + 64 + tx * 4);
    const float4 arA = *(const float4*)(ars + tx * 4);
    const float4 arB = *(const float4*)(ars + 64 + tx * 4);
    const unsigned FULL = 0xffffffffu;
    const int lane = tid & 31;
    const int hA = tx >> 3;            // head of chunk A; chunk B head = hA+2

#pragma unroll
    for (int j = 0; j < 4; ++j) {
        int row = rb + ty * 4 + j;
        float2 a0 = upk(acc[j][0]), a1 = upk(acc[j][1]);
        float2 b0 = upk(acc[j][2]), b1 = upk(acc[j][3]);
        if (row < n_nodes) {
            *(float4*)(g_feat + row * FD + tx * 4)      = make_float4(a0.x, a0.y, a1.x, a1.y);
            *(float4*)(g_feat + row * FD + 64 + tx * 4) = make_float4(b0.x, b0.y, b1.x, b1.y);
        }
        float plA = a0.x * alA.x + a0.y * alA.y + a1.x * alA.z + a1.y * alA.w;
        float prA = a0.x * arA.x + a0.y * arA.y + a1.x * arA.z + a1.y * arA.w;
        float plB = b0.x * alB.x + b0.y * alB.y + b1.x * alB.z + b1.y * alB.w;
        float prB = b0.x * arB.x + b0.y * arB.y + b1.x * arB.z + b1.y * arB.w;
#pragma unroll
        for (int off = 4; off; off >>= 1) {   // reduce across 8 tx lanes (one head)
            plA += __shfl_xor_sync(FULL, plA, off);
            prA += __shfl_xor_sync(FULL, prA, off);
            plB += __shfl_xor_sync(FULL, plB, off);
            prB += __shfl_xor_sync(FULL, prB, off);
        }
        if ((lane & 7) == 0 && row < n_nodes) {
            g_el[row * NH + hA]     = plA;
            g_er[row * NH + hA]     = prA;
            g_el[row * NH + hA + 2] = plB;
            g_er[row * NH + hA + 2] = prB;
        }
    }
}

// ---------------------------------------------------------------------------
// Kernel 2: single-pass edge softmax + aggregation (no max-shift needed:
// exp(e)/sum(exp(e)) == exp(e-m)/sum(exp(e-m)); logits are O(1) here).
// One warp per dst node; lanes cover the 512B feat row (coalesced).
// ---------------------------------------------------------------------------
__global__ void __launch_bounds__(256) gat_agg(
    const int* __restrict__ src, float* __restrict__ out, int n_nodes)
{
    const int lane = threadIdx.x & 31;
    const int n = (blockIdx.x * blockDim.x + threadIdx.x) >> 5;
    if (n >= n_nodes) return;

    const int s = g_rowstart[n];
    const int e = g_rowstart[n + 1];
    const int h = lane >> 3;
    const float ern = g_er[n * NH + h];

    float denom = 0.f;
    float ax = 0.f, ay = 0.f, az = 0.f, aw = 0.f;

#pragma unroll 2
    for (int i = s; i < e; ++i) {
        int sv = __ldg(src + i);
        float lg = g_el[sv * NH + h] + ern;
        lg = lg > 0.f ? lg : 0.2f * lg;
        float w = __expf(lg);
        denom += w;
        float4 f = *(const float4*)(g_feat + sv * FD + lane * 4);
        ax = fmaf(w, f.x, ax); ay = fmaf(w, f.y, ay);
        az = fmaf(w, f.z, az); aw = fmaf(w, f.w, aw);
    }
    float r = (e > s) ? 1.0f / denom : 0.f;
    *(float4*)(out + n * FD + lane * 4) =
        make_float4(ax * r, ay * r, az * r, aw * r);
}

// ---------------------------------------------------------------------------
extern "C" void kernel_launch(void* const* d_in, const int* in_sizes, int n_in,
                              void* d_out, int out_size)
{
    const float* x   = (const float*)d_in[0];
    const float* W   = (const float*)d_in[1];
    const float* al  = (const float*)d_in[2];
    const float* ar  = (const float*)d_in[3];
    const int*   src = (const int*)d_in[4];
    const int*   dst = (const int*)d_in[5];
    float* out = (float*)d_out;

    const int n_nodes = in_sizes[0] / FD;
    const int n_edges = in_sizes[4];

    gat_wt<<<dim3(4, 4), dim3(32, 8)>>>(W);
    gat_seg<<<(n_edges + 255) / 256, 256>>>(dst, n_edges, n_nodes);

    const size_t smem = (size_t)(BM * FD + FD * FD + 2 * FD) * sizeof(float);
    cudaFuncSetAttribute(gat_gemm, cudaFuncAttributeMaxDynamicSharedMemorySize, (int)smem);
    gat_gemm<<<(n_nodes + BM - 1) / BM, 256, smem>>>(x, al, ar, n_nodes);

    gat_agg<<<(n_nodes * 32 + 255) / 256, 256>>>(src, out, n_nodes);
}